// round 1
// baseline (speedup 1.0000x reference)
#include <cuda_runtime.h>
#include <cuda_bf16.h>
#include <math.h>

// ---------------- problem constants ----------------
#define BATCH   16
#define SEQ     768
#define MTOK    (BATCH*SEQ)       // 12288
#define DMODEL  512
#define DSTATE  128
#define DCONV   4
#define DINNER  1024
#define HEADDIM 64
#define NHEADS  16
#define CONVDIM (DINNER + 2*DSTATE)        // 1280
#define DINPROJ (2*DINNER + 2*DSTATE + NHEADS) // 2320
#define NLAYER  28
#define VOCAB   256
#define EPSF    1e-5f

// ---------------- device scratch ----------------
__device__ float g_hidden[MTOK*DMODEL];
__device__ float g_resid [MTOK*DMODEL];
__device__ float g_norm  [MTOK*DMODEL];
__device__ float g_zx    [(size_t)MTOK*DINPROJ];
__device__ float g_xbc   [(size_t)MTOK*CONVDIM];
__device__ float g_dt    [MTOK*NHEADS];
__device__ float g_y     [(size_t)MTOK*DINNER];
__device__ float g_gated [(size_t)MTOK*DINNER];
__device__ float g_logits[(size_t)MTOK*VOCAB];
__device__ float g_loss_sum;

// ---------------- helpers ----------------
__device__ __forceinline__ float blockReduceSum(float v) {
    __shared__ float sh[32];
    int lane = threadIdx.x & 31, wid = threadIdx.x >> 5;
    #pragma unroll
    for (int o = 16; o > 0; o >>= 1) v += __shfl_xor_sync(0xffffffffu, v, o);
    if (lane == 0) sh[wid] = v;
    __syncthreads();
    if (threadIdx.x == 0) {
        float t = 0.f;
        int nw = (blockDim.x + 31) >> 5;
        for (int i = 0; i < nw; i++) t += sh[i];
        sh[0] = t;
    }
    __syncthreads();
    return sh[0];
}

__device__ __forceinline__ float siluf(float x) {
    return x / (1.0f + expf(-x));
}

// ---------------- embedding + residual init ----------------
__global__ void embed_kernel(const int* __restrict__ tokens,
                             const float* __restrict__ emb,
                             float* __restrict__ hid, float* __restrict__ res) {
    int idx = blockIdx.x * blockDim.x + threadIdx.x;
    if (idx >= MTOK * DMODEL) return;
    int m = idx >> 9;     // /512
    int d = idx & 511;
    hid[idx] = emb[tokens[m] * DMODEL + d];
    res[idx] = 0.0f;
}

// res += h ; out = rms(res)*w  (D = 512, 128 threads, 4 elems/thread)
__global__ void add_rms_kernel(const float* __restrict__ h, float* __restrict__ res,
                               const float* __restrict__ w, float* __restrict__ out) {
    int m = blockIdx.x;
    const float* hr = h + (size_t)m * DMODEL;
    float* rr = res + (size_t)m * DMODEL;
    float v[4]; float ss = 0.f;
    #pragma unroll
    for (int j = 0; j < 4; j++) {
        int d = threadIdx.x + j * 128;
        float x = hr[d] + rr[d];
        rr[d] = x;
        v[j] = x;
        ss += x * x;
    }
    float tot = blockReduceSum(ss);
    float scale = rsqrtf(tot * (1.0f / DMODEL) + EPSF);
    #pragma unroll
    for (int j = 0; j < 4; j++) {
        int d = threadIdx.x + j * 128;
        out[(size_t)m * DMODEL + d] = v[j] * scale * w[d];
    }
}

// ---------------- SGEMM: C[M,N] = A[M,K] * B[N,K]^T  (fp32) ----------------
// BM=BN=128, BK=16, 256 threads, 8x8 microtile. M must be multiple of 128,
// K multiple of 16. N guarded.
__global__ void sgemm_nt(const float* __restrict__ A, const float* __restrict__ B,
                         float* __restrict__ C, int M, int N, int K) {
    __shared__ __align__(16) float As[16][128];
    __shared__ __align__(16) float Bs[16][128];
    const int tid  = threadIdx.x;
    const int bm   = blockIdx.y * 128;
    const int bn   = blockIdx.x * 128;
    const int tx   = tid & 15;        // n dir
    const int ty   = tid >> 4;        // m dir
    const int lrow = tid >> 2;        // 0..63
    const int lcol = (tid & 3) << 2;  // 0,4,8,12

    float acc[8][8];
    #pragma unroll
    for (int i = 0; i < 8; i++)
        #pragma unroll
        for (int j = 0; j < 8; j++) acc[i][j] = 0.f;

    for (int k0 = 0; k0 < K; k0 += 16) {
        #pragma unroll
        for (int r = 0; r < 2; r++) {
            int m = bm + lrow + r * 64;
            float4 v = *reinterpret_cast<const float4*>(A + (size_t)m * K + k0 + lcol);
            As[lcol + 0][lrow + r * 64] = v.x;
            As[lcol + 1][lrow + r * 64] = v.y;
            As[lcol + 2][lrow + r * 64] = v.z;
            As[lcol + 3][lrow + r * 64] = v.w;
        }
        #pragma unroll
        for (int r = 0; r < 2; r++) {
            int n = bn + lrow + r * 64;
            float4 v = make_float4(0.f, 0.f, 0.f, 0.f);
            if (n < N) v = *reinterpret_cast<const float4*>(B + (size_t)n * K + k0 + lcol);
            Bs[lcol + 0][lrow + r * 64] = v.x;
            Bs[lcol + 1][lrow + r * 64] = v.y;
            Bs[lcol + 2][lrow + r * 64] = v.z;
            Bs[lcol + 3][lrow + r * 64] = v.w;
        }
        __syncthreads();
        #pragma unroll
        for (int kk = 0; kk < 16; kk++) {
            float4 a0 = *reinterpret_cast<const float4*>(&As[kk][ty * 8]);
            float4 a1 = *reinterpret_cast<const float4*>(&As[kk][ty * 8 + 4]);
            float4 b0 = *reinterpret_cast<const float4*>(&Bs[kk][tx * 8]);
            float4 b1 = *reinterpret_cast<const float4*>(&Bs[kk][tx * 8 + 4]);
            float a[8] = {a0.x, a0.y, a0.z, a0.w, a1.x, a1.y, a1.z, a1.w};
            float b[8] = {b0.x, b0.y, b0.z, b0.w, b1.x, b1.y, b1.z, b1.w};
            #pragma unroll
            for (int i = 0; i < 8; i++)
                #pragma unroll
                for (int j = 0; j < 8; j++)
                    acc[i][j] = fmaf(a[i], b[j], acc[i][j]);
        }
        __syncthreads();
    }
    #pragma unroll
    for (int i = 0; i < 8; i++) {
        int m = bm + ty * 8 + i;
        #pragma unroll
        for (int j = 0; j < 8; j++) {
            int n = bn + tx * 8 + j;
            if (n < N) C[(size_t)m * N + n] = acc[i][j];
        }
    }
}

// ---------------- dt = softplus(zx[:,2304+h] + dt_bias[h]) ----------------
__global__ void dt_kernel(const float* __restrict__ zx, const float* __restrict__ dt_bias,
                          float* __restrict__ dt) {
    int idx = blockIdx.x * blockDim.x + threadIdx.x;
    if (idx >= MTOK * NHEADS) return;
    int m = idx >> 4;
    int h = idx & 15;
    float x = zx[(size_t)m * DINPROJ + (2 * DINNER + 2 * DSTATE) + h] + dt_bias[h];
    dt[idx] = (x > 20.0f) ? x : log1pf(expf(x));
}

// ---------------- causal depthwise conv (taps=4) + silu ----------------
__global__ void conv_silu_kernel(const float* __restrict__ zx, const float* __restrict__ w,
                                 const float* __restrict__ bias, float* __restrict__ out) {
    int idx = blockIdx.x * blockDim.x + threadIdx.x;
    if (idx >= MTOK * CONVDIM) return;
    int c = idx % CONVDIM;
    int m = idx / CONVDIM;
    int l = m % SEQ;
    int b = m / SEQ;
    float acc = bias[c];
    #pragma unroll
    for (int k = 0; k < DCONV; k++) {
        int lp = l + k - (DCONV - 1);
        if (lp >= 0)
            acc = fmaf(zx[((size_t)(b * SEQ + lp)) * DINPROJ + DINNER + c], w[c * DCONV + k], acc);
    }
    out[(size_t)m * CONVDIM + c] = siluf(acc);
}

// ---------------- SSD sequential scan ----------------
// grid = 256 (b*16+h) blocks, 128 threads. Thread t owns p = t>>1, n-half = t&1
// (64 state elems in registers).
__global__ void ssd_scan_kernel(const float* __restrict__ xbc, const float* __restrict__ dt,
                                const float* __restrict__ A_log, const float* __restrict__ Dv,
                                float* __restrict__ y) {
    const int bh = blockIdx.x;
    const int b = bh >> 4, hh = bh & 15;
    const int t = threadIdx.x;
    const int p = t >> 1;
    const int nh = t & 1;
    const float A = -expf(A_log[hh]);
    const float Dh = Dv[hh];
    float hs[64];
    #pragma unroll
    for (int i = 0; i < 64; i++) hs[i] = 0.f;

    __shared__ __align__(16) float sB[128], sC[128], sX[64];
    const size_t base = (size_t)b * SEQ;

    for (int l = 0; l < SEQ; ++l) {
        const float* row = xbc + (base + l) * CONVDIM;
        sB[t] = row[DINNER + t];
        sC[t] = row[DINNER + DSTATE + t];
        if (t < 64) sX[t] = row[hh * HEADDIM + t];
        float dtv = dt[(base + l) * NHEADS + hh];
        __syncthreads();
        float dA  = expf(dtv * A);
        float xp  = sX[p];
        float dbx = dtv * xp;
        float accv = 0.f;
        const float4* B4 = reinterpret_cast<const float4*>(sB + nh * 64);
        const float4* C4 = reinterpret_cast<const float4*>(sC + nh * 64);
        #pragma unroll
        for (int i = 0; i < 16; i++) {
            float4 bv = B4[i], cv = C4[i];
            hs[4*i+0] = fmaf(dA, hs[4*i+0], dbx * bv.x); accv = fmaf(hs[4*i+0], cv.x, accv);
            hs[4*i+1] = fmaf(dA, hs[4*i+1], dbx * bv.y); accv = fmaf(hs[4*i+1], cv.y, accv);
            hs[4*i+2] = fmaf(dA, hs[4*i+2], dbx * bv.z); accv = fmaf(hs[4*i+2], cv.z, accv);
            hs[4*i+3] = fmaf(dA, hs[4*i+3], dbx * bv.w); accv = fmaf(hs[4*i+3], cv.w, accv);
        }
        accv += __shfl_xor_sync(0xffffffffu, accv, 1);
        if (nh == 0)
            y[(base + l) * DINNER + hh * HEADDIM + p] = accv + Dh * xp;
        __syncthreads();
    }
}

// ---------------- gated RMSNorm: out = rms(y*silu(z)) * gw ----------------
__global__ void gate_rms_kernel(const float* __restrict__ zx, const float* __restrict__ y,
                                const float* __restrict__ gw, float* __restrict__ out) {
    int m = blockIdx.x;
    const float* zr = zx + (size_t)m * DINPROJ;
    const float* yr = y + (size_t)m * DINNER;
    float v[4]; float ss = 0.f;
    #pragma unroll
    for (int j = 0; j < 4; j++) {
        int d = threadIdx.x + j * 256;
        float z = zr[d];
        float g = yr[d] * siluf(z);
        v[j] = g;
        ss += g * g;
    }
    float tot = blockReduceSum(ss);
    float scale = rsqrtf(tot * (1.0f / DINNER) + EPSF);
    #pragma unroll
    for (int j = 0; j < 4; j++) {
        int d = threadIdx.x + j * 256;
        out[(size_t)m * DINNER + d] = v[j] * scale * gw[d];
    }
}

// ---------------- loss ----------------
__global__ void zero_loss_kernel(float* p) { *p = 0.f; }

__global__ void loss_kernel(const float* __restrict__ logits, const int* __restrict__ targets,
                            float* __restrict__ acc) {
    int gwid = (blockIdx.x * blockDim.x + threadIdx.x) >> 5;
    int lane = threadIdx.x & 31;
    if (gwid >= MTOK) return;
    const float* row = logits + (size_t)gwid * VOCAB;
    float mx = -1e30f;
    #pragma unroll
    for (int i = lane; i < VOCAB; i += 32) mx = fmaxf(mx, row[i]);
    #pragma unroll
    for (int o = 16; o > 0; o >>= 1) mx = fmaxf(mx, __shfl_xor_sync(0xffffffffu, mx, o));
    float s = 0.f;
    #pragma unroll
    for (int i = lane; i < VOCAB; i += 32) s += expf(row[i] - mx);
    #pragma unroll
    for (int o = 16; o > 0; o >>= 1) s += __shfl_xor_sync(0xffffffffu, s, o);
    if (lane == 0) {
        float lse = mx + logf(s);
        atomicAdd(acc, lse - row[targets[gwid]]);
    }
}

__global__ void fin_loss_kernel(const float* sum, float* dst) {
    *dst = (*sum) * (1.0f / (float)MTOK);
}

__global__ void copy_kernel(const float* __restrict__ src, float* __restrict__ dst, int n) {
    int i = blockIdx.x * blockDim.x + threadIdx.x;
    if (i < n) dst[i] = src[i];
}

// ---------------- host launcher ----------------
extern "C" void kernel_launch(void* const* d_in, const int* in_sizes, int n_in,
                              void* d_out, int out_size) {
    const int*   tokens   = (const int*)  d_in[0];
    const int*   targets  = (const int*)  d_in[1];
    const float* emb      = (const float*)d_in[2];
    const float* in_proj  = (const float*)d_in[3];
    const float* conv_w   = (const float*)d_in[4];
    const float* conv_b   = (const float*)d_in[5];
    const float* dt_bias  = (const float*)d_in[6];
    const float* A_log    = (const float*)d_in[7];
    const float* Dv       = (const float*)d_in[8];
    const float* gnorm    = (const float*)d_in[9];
    const float* out_proj = (const float*)d_in[10];
    const float* bnorm    = (const float*)d_in[11];
    const float* fnorm    = (const float*)d_in[12];
    float* out = (float*)d_out;

    float *hid, *res, *nrm, *zx, *xbc, *dtp, *yb, *gat, *lgt, *lsum;
    cudaGetSymbolAddress((void**)&hid,  g_hidden);
    cudaGetSymbolAddress((void**)&res,  g_resid);
    cudaGetSymbolAddress((void**)&nrm,  g_norm);
    cudaGetSymbolAddress((void**)&zx,   g_zx);
    cudaGetSymbolAddress((void**)&xbc,  g_xbc);
    cudaGetSymbolAddress((void**)&dtp,  g_dt);
    cudaGetSymbolAddress((void**)&yb,   g_y);
    cudaGetSymbolAddress((void**)&gat,  g_gated);
    cudaGetSymbolAddress((void**)&lgt,  g_logits);
    cudaGetSymbolAddress((void**)&lsum, g_loss_sum);

    embed_kernel<<<(MTOK * DMODEL + 255) / 256, 256>>>(tokens, emb, hid, res);

    for (int L = 0; L < NLAYER; ++L) {
        add_rms_kernel<<<MTOK, 128>>>(hid, res, bnorm + (size_t)L * DMODEL, nrm);

        dim3 g1((DINPROJ + 127) / 128, MTOK / 128);
        sgemm_nt<<<g1, 256>>>(nrm, in_proj + (size_t)L * DINPROJ * DMODEL, zx,
                              MTOK, DINPROJ, DMODEL);

        dt_kernel<<<(MTOK * NHEADS + 255) / 256, 256>>>(zx, dt_bias + (size_t)L * NHEADS, dtp);

        conv_silu_kernel<<<(MTOK * CONVDIM + 255) / 256, 256>>>(
            zx, conv_w + (size_t)L * CONVDIM * DCONV, conv_b + (size_t)L * CONVDIM, xbc);

        ssd_scan_kernel<<<BATCH * NHEADS, 128>>>(xbc, dtp,
                                                 A_log + (size_t)L * NHEADS,
                                                 Dv + (size_t)L * NHEADS, yb);

        gate_rms_kernel<<<MTOK, 256>>>(zx, yb, gnorm + (size_t)L * DINNER, gat);

        dim3 g2((DMODEL + 127) / 128, MTOK / 128);
        sgemm_nt<<<g2, 256>>>(gat, out_proj + (size_t)L * DMODEL * DINNER, hid,
                              MTOK, DMODEL, DINNER);
    }

    add_rms_kernel<<<MTOK, 128>>>(hid, res, fnorm, nrm);

    dim3 g3((VOCAB + 127) / 128, MTOK / 128);
    sgemm_nt<<<g3, 256>>>(nrm, emb, lgt, MTOK, VOCAB, DMODEL);

    zero_loss_kernel<<<1, 1>>>(lsum);
    loss_kernel<<<(MTOK * 32 + 255) / 256, 256>>>(lgt, targets, lsum);

    const int LG = MTOK * VOCAB;  // 3145728
    if (out_size >= LG) {
        copy_kernel<<<(LG + 255) / 256, 256>>>(lgt, out, LG);
        if (out_size > LG) fin_loss_kernel<<<1, 1>>>(lsum, out + (out_size - 1));
    } else {
        fin_loss_kernel<<<1, 1>>>(lsum, out);
    }
}

// round 3
// speedup vs baseline: 1.5621x; 1.5621x over previous
#include <cuda_runtime.h>
#include <cuda_bf16.h>
#include <math.h>
#include <stdint.h>

// ---------------- problem constants ----------------
#define BATCH   16
#define SEQ     768
#define MTOK    (BATCH*SEQ)       // 12288
#define DMODEL  512
#define DSTATE  128
#define DCONV   4
#define DINNER  1024
#define HEADDIM 64
#define NHEADS  16
#define CONVDIM (DINNER + 2*DSTATE)            // 1280
#define DINPROJ (2*DINNER + 2*DSTATE + NHEADS) // 2320
#define NINPAD  2432                            // 19*128
#define NLAYER  28
#define VOCAB   256
#define EPSF    1e-5f

// ---------------- device scratch ----------------
__device__ float g_hidden[MTOK*DMODEL];
__device__ float g_resid [MTOK*DMODEL];
__device__ float g_zx    [(size_t)MTOK*DINPROJ];
__device__ float g_xbc   [(size_t)MTOK*CONVDIM];
__device__ float g_dt    [MTOK*NHEADS];
__device__ float g_y     [(size_t)MTOK*DINNER];
__device__ float g_logits[(size_t)MTOK*VOCAB];
__device__ float g_loss_sum;

__device__ __nv_bfloat16 g_nh[MTOK*DMODEL],  g_nl[MTOK*DMODEL];
__device__ __nv_bfloat16 g_gh[MTOK*DINNER],  g_gl[MTOK*DINNER];
__device__ __nv_bfloat16 g_wih[(size_t)NLAYER*NINPAD*DMODEL], g_wil[(size_t)NLAYER*NINPAD*DMODEL];
__device__ __nv_bfloat16 g_woh[(size_t)NLAYER*DMODEL*DINNER], g_wol[(size_t)NLAYER*DMODEL*DINNER];
__device__ __nv_bfloat16 g_eh[VOCAB*DMODEL], g_el[VOCAB*DMODEL];

// ---------------- PTX helpers (family-safe: sm_80-class only) ----------------
__device__ __forceinline__ uint32_t smem_u32(const void* p) {
    uint32_t a;
    asm("{ .reg .u64 t; cvta.to.shared.u64 t, %1; cvt.u32.u64 %0, t; }" : "=r"(a) : "l"(p));
    return a;
}
__device__ __forceinline__ void cp16(uint32_t dst, const void* src) {
    asm volatile("cp.async.cg.shared.global [%0], [%1], 16;" :: "r"(dst), "l"(src));
}
__device__ __forceinline__ void ldm_x4(uint32_t addr, uint32_t& r0, uint32_t& r1, uint32_t& r2, uint32_t& r3) {
    asm volatile("ldmatrix.sync.aligned.m8n8.x4.shared.b16 {%0,%1,%2,%3}, [%4];"
                 : "=r"(r0), "=r"(r1), "=r"(r2), "=r"(r3) : "r"(addr));
}
__device__ __forceinline__ void mma_bf16(float* c, const uint32_t* a, const uint32_t* b) {
    asm volatile(
        "mma.sync.aligned.m16n8k16.row.col.f32.bf16.bf16.f32 "
        "{%0,%1,%2,%3}, {%4,%5,%6,%7}, {%8,%9}, {%0,%1,%2,%3};"
        : "+f"(c[0]), "+f"(c[1]), "+f"(c[2]), "+f"(c[3])
        : "r"(a[0]), "r"(a[1]), "r"(a[2]), "r"(a[3]), "r"(b[0]), "r"(b[1]));
}

// ---------------- bf16x3 GEMM via mma.sync ----------------
// C[M,N] = A[M,K]*B[N,K]^T, fp32 C. A,B given as bf16 hi/lo pairs.
// Tile 128x128, KC=32, 3-stage cp.async pipeline, 256 threads (8 warps 2x4).
// smem row layout: 32 bf16 = 64B data + 16B pad = 80B stride (conflict-free ldmatrix).
#define ROWB   80
#define SUBT   (128*ROWB)      // 10240 per subtile
#define STAGEB (4*SUBT)        // 40960: Ah, Al, Bh, Bl
#define GSMEM  (3*STAGEB)      // 122880

__device__ __forceinline__ void fill_stage(uint32_t st,
        const __nv_bfloat16* __restrict__ Ah, const __nv_bfloat16* __restrict__ Al,
        const __nv_bfloat16* __restrict__ Bh, const __nv_bfloat16* __restrict__ Bl,
        int bm, int bn, int K, int kc, int tid)
{
    const size_t k0 = (size_t)kc * 32;
    const __nv_bfloat16* srcs[4] = {Ah + (size_t)bm * K + k0, Al + (size_t)bm * K + k0,
                                    Bh + (size_t)bn * K + k0, Bl + (size_t)bn * K + k0};
    #pragma unroll
    for (int s = 0; s < 4; ++s) {
        const __nv_bfloat16* base = srcs[s];
        uint32_t sd = st + s * SUBT;
        #pragma unroll
        for (int i = 0; i < 2; ++i) {
            int lin = tid + (i << 8);         // 0..511
            int row = lin >> 2;               // 0..127
            int ch  = lin & 3;                // 16B chunk
            cp16(sd + row * ROWB + ch * 16, base + (size_t)row * K + ch * 8);
        }
    }
    asm volatile("cp.async.commit_group;" ::: "memory");
}

__global__ void __launch_bounds__(256) gemm_bf16x3(
    const __nv_bfloat16* __restrict__ Ah, const __nv_bfloat16* __restrict__ Al,
    const __nv_bfloat16* __restrict__ Bh, const __nv_bfloat16* __restrict__ Bl,
    float* __restrict__ C, int M, int N, int K)
{
    extern __shared__ char smem[];
    const uint32_t sb = smem_u32(smem);
    const int tid  = threadIdx.x;
    const int wid  = tid >> 5, lane = tid & 31;
    const int wm   = wid >> 2, wn = wid & 3;          // 2 x 4 warp grid
    const int bm   = blockIdx.y * 128, bn = blockIdx.x * 128;

    float acc[4][4][4];
    #pragma unroll
    for (int i = 0; i < 4; i++)
        #pragma unroll
        for (int j = 0; j < 4; j++)
            #pragma unroll
            for (int q = 0; q < 4; q++) acc[i][j][q] = 0.f;

    const int nc = K >> 5;   // K / 32

    fill_stage(sb + 0 * STAGEB, Ah, Al, Bh, Bl, bm, bn, K, 0, tid);
    fill_stage(sb + 1 * STAGEB, Ah, Al, Bh, Bl, bm, bn, K, 1, tid);

    // ldmatrix lane addressing
    const int a_r  = lane & 15;            // row within 16
    const int a_k  = lane >> 4;            // k-half (16B)
    const int b_r  = ((lane >> 4) << 3) + (lane & 7); // n row within 16
    const int b_k  = (lane >> 3) & 1;      // k-half

    for (int c = 0; c < nc; ++c) {
        const uint32_t st = sb + (uint32_t)(c % 3) * STAGEB;
        // wait for fill(c): at most 1 newer group outstanding
        asm volatile("cp.async.wait_group 1;" ::: "memory");
        __syncthreads();

        int cn = c + 2;
        if (cn < nc)
            fill_stage(sb + (uint32_t)(cn % 3) * STAGEB, Ah, Al, Bh, Bl, bm, bn, K, cn, tid);

        const uint32_t a_base = st + (uint32_t)(wm * 64 + a_r) * ROWB + a_k * 16;
        const uint32_t b_base = st + 2 * SUBT + (uint32_t)(wn * 32 + b_r) * ROWB + b_k * 16;

        #pragma unroll
        for (int ks = 0; ks < 2; ++ks) {
            uint32_t ah[4][4], al[4][4], bh[4][2], bl[4][2];
            #pragma unroll
            for (int mi = 0; mi < 4; ++mi) {
                uint32_t addr = a_base + (uint32_t)(mi * 16) * ROWB + ks * 32;
                ldm_x4(addr,        ah[mi][0], ah[mi][1], ah[mi][2], ah[mi][3]);
                ldm_x4(addr + SUBT, al[mi][0], al[mi][1], al[mi][2], al[mi][3]);
            }
            #pragma unroll
            for (int bi = 0; bi < 2; ++bi) {
                uint32_t addr = b_base + (uint32_t)(bi * 16) * ROWB + ks * 32;
                ldm_x4(addr,        bh[2*bi][0], bh[2*bi][1], bh[2*bi+1][0], bh[2*bi+1][1]);
                ldm_x4(addr + SUBT, bl[2*bi][0], bl[2*bi][1], bl[2*bi+1][0], bl[2*bi+1][1]);
            }
            #pragma unroll
            for (int mi = 0; mi < 4; ++mi)
                #pragma unroll
                for (int ni = 0; ni < 4; ++ni) {
                    mma_bf16(acc[mi][ni], ah[mi], bh[ni]);
                    mma_bf16(acc[mi][ni], ah[mi], bl[ni]);
                    mma_bf16(acc[mi][ni], al[mi], bh[ni]);
                }
        }
        __syncthreads();   // protect stage reuse before next fill overwrites
    }

    // epilogue
    const int r  = lane >> 2;
    const int cc = (lane & 3) << 1;
    #pragma unroll
    for (int mi = 0; mi < 4; ++mi) {
        int m0 = bm + wm * 64 + mi * 16 + r;
        #pragma unroll
        for (int ni = 0; ni < 4; ++ni) {
            int n0 = bn + wn * 32 + ni * 8 + cc;
            if (n0 < N) {
                *reinterpret_cast<float2*>(C + (size_t)m0 * N + n0) =
                    make_float2(acc[mi][ni][0], acc[mi][ni][1]);
                *reinterpret_cast<float2*>(C + (size_t)(m0 + 8) * N + n0) =
                    make_float2(acc[mi][ni][2], acc[mi][ni][3]);
            }
        }
    }
}

// ---------------- generic helpers ----------------
__device__ __forceinline__ float blockReduceSum(float v) {
    __shared__ float sh[32];
    int lane = threadIdx.x & 31, wid = threadIdx.x >> 5;
    #pragma unroll
    for (int o = 16; o > 0; o >>= 1) v += __shfl_xor_sync(0xffffffffu, v, o);
    if (lane == 0) sh[wid] = v;
    __syncthreads();
    if (threadIdx.x == 0) {
        float t = 0.f;
        int nw = (blockDim.x + 31) >> 5;
        for (int i = 0; i < nw; i++) t += sh[i];
        sh[0] = t;
    }
    __syncthreads();
    return sh[0];
}
__device__ __forceinline__ float siluf(float x) { return x / (1.0f + expf(-x)); }

__device__ __forceinline__ void bf16split(float v, __nv_bfloat16* h, __nv_bfloat16* l) {
    __nv_bfloat16 hb = __float2bfloat16(v);
    *h = hb;
    *l = __float2bfloat16(v - __bfloat162float(hb));
}

// ---------------- weight split (with row padding) ----------------
__global__ void split_pad_kernel(const float* __restrict__ src, __nv_bfloat16* __restrict__ h,
                                 __nv_bfloat16* __restrict__ l, int nt, int np, int K, long total) {
    long idx = (long)blockIdx.x * blockDim.x + threadIdx.x;
    if (idx >= total) return;
    int k = (int)(idx % K);
    long t = idx / K;
    int r  = (int)(t % np);
    int ly = (int)(t / np);
    float v = (r < nt) ? src[((size_t)ly * nt + r) * K + k] : 0.0f;
    __nv_bfloat16 hh, ll;
    bf16split(v, &hh, &ll);
    h[idx] = hh; l[idx] = ll;
}

// ---------------- embedding + residual init ----------------
__global__ void embed_kernel(const int* __restrict__ tokens, const float* __restrict__ emb,
                             float* __restrict__ hid, float* __restrict__ res) {
    int idx = blockIdx.x * blockDim.x + threadIdx.x;
    if (idx >= MTOK * DMODEL) return;
    int m = idx >> 9;
    int d = idx & 511;
    hid[idx] = emb[tokens[m] * DMODEL + d];
    res[idx] = 0.0f;
}

// res += h ; out = rms(res)*w, emitted as bf16 hi/lo
__global__ void add_rms_kernel(const float* __restrict__ h, float* __restrict__ res,
                               const float* __restrict__ w,
                               __nv_bfloat16* __restrict__ oh, __nv_bfloat16* __restrict__ ol) {
    int m = blockIdx.x;
    const float* hr = h + (size_t)m * DMODEL;
    float* rr = res + (size_t)m * DMODEL;
    float v[4]; float ss = 0.f;
    #pragma unroll
    for (int j = 0; j < 4; j++) {
        int d = threadIdx.x + j * 128;
        float x = hr[d] + rr[d];
        rr[d] = x;
        v[j] = x;
        ss += x * x;
    }
    float tot = blockReduceSum(ss);
    float scale = rsqrtf(tot * (1.0f / DMODEL) + EPSF);
    #pragma unroll
    for (int j = 0; j < 4; j++) {
        int d = threadIdx.x + j * 128;
        float o = v[j] * scale * w[d];
        __nv_bfloat16 hh, ll;
        bf16split(o, &hh, &ll);
        oh[(size_t)m * DMODEL + d] = hh;
        ol[(size_t)m * DMODEL + d] = ll;
    }
}

// ---------------- dt = softplus ----------------
__global__ void dt_kernel(const float* __restrict__ zx, const float* __restrict__ dt_bias,
                          float* __restrict__ dt) {
    int idx = blockIdx.x * blockDim.x + threadIdx.x;
    if (idx >= MTOK * NHEADS) return;
    int m = idx >> 4;
    int h = idx & 15;
    float x = zx[(size_t)m * DINPROJ + (2 * DINNER + 2 * DSTATE) + h] + dt_bias[h];
    dt[idx] = (x > 20.0f) ? x : log1pf(expf(x));
}

// ---------------- causal depthwise conv + silu ----------------
__global__ void conv_silu_kernel(const float* __restrict__ zx, const float* __restrict__ w,
                                 const float* __restrict__ bias, float* __restrict__ out) {
    int idx = blockIdx.x * blockDim.x + threadIdx.x;
    if (idx >= MTOK * CONVDIM) return;
    int c = idx % CONVDIM;
    int m = idx / CONVDIM;
    int l = m % SEQ;
    int b = m / SEQ;
    float acc = bias[c];
    #pragma unroll
    for (int k = 0; k < DCONV; k++) {
        int lp = l + k - (DCONV - 1);
        if (lp >= 0)
            acc = fmaf(zx[((size_t)(b * SEQ + lp)) * DINPROJ + DINNER + c], w[c * DCONV + k], acc);
    }
    out[(size_t)m * CONVDIM + c] = siluf(acc);
}

// ---------------- SSD sequential scan ----------------
__global__ void ssd_scan_kernel(const float* __restrict__ xbc, const float* __restrict__ dt,
                                const float* __restrict__ A_log, const float* __restrict__ Dv,
                                float* __restrict__ y) {
    const int bh = blockIdx.x;
    const int b = bh >> 4, hh = bh & 15;
    const int t = threadIdx.x;
    const int p = t >> 1;
    const int nh = t & 1;
    const float A = -expf(A_log[hh]);
    const float Dh = Dv[hh];
    float hs[64];
    #pragma unroll
    for (int i = 0; i < 64; i++) hs[i] = 0.f;

    __shared__ __align__(16) float sB[128], sC[128], sX[64];
    const size_t base = (size_t)b * SEQ;

    for (int l = 0; l < SEQ; ++l) {
        const float* row = xbc + (base + l) * CONVDIM;
        sB[t] = row[DINNER + t];
        sC[t] = row[DINNER + DSTATE + t];
        if (t < 64) sX[t] = row[hh * HEADDIM + t];
        float dtv = dt[(base + l) * NHEADS + hh];
        __syncthreads();
        float dA  = expf(dtv * A);
        float xp  = sX[p];
        float dbx = dtv * xp;
        float accv = 0.f;
        const float4* B4 = reinterpret_cast<const float4*>(sB + nh * 64);
        const float4* C4 = reinterpret_cast<const float4*>(sC + nh * 64);
        #pragma unroll
        for (int i = 0; i < 16; i++) {
            float4 bv = B4[i], cv = C4[i];
            hs[4*i+0] = fmaf(dA, hs[4*i+0], dbx * bv.x); accv = fmaf(hs[4*i+0], cv.x, accv);
            hs[4*i+1] = fmaf(dA, hs[4*i+1], dbx * bv.y); accv = fmaf(hs[4*i+1], cv.y, accv);
            hs[4*i+2] = fmaf(dA, hs[4*i+2], dbx * bv.z); accv = fmaf(hs[4*i+2], cv.z, accv);
            hs[4*i+3] = fmaf(dA, hs[4*i+3], dbx * bv.w); accv = fmaf(hs[4*i+3], cv.w, accv);
        }
        accv += __shfl_xor_sync(0xffffffffu, accv, 1);
        if (nh == 0)
            y[(base + l) * DINNER + hh * HEADDIM + p] = accv + Dh * xp;
        __syncthreads();
    }
}

// ---------------- gated RMSNorm -> bf16 hi/lo ----------------
__global__ void gate_rms_kernel(const float* __restrict__ zx, const float* __restrict__ y,
                                const float* __restrict__ gw,
                                __nv_bfloat16* __restrict__ oh, __nv_bfloat16* __restrict__ ol) {
    int m = blockIdx.x;
    const float* zr = zx + (size_t)m * DINPROJ;
    const float* yr = y + (size_t)m * DINNER;
    float v[4]; float ss = 0.f;
    #pragma unroll
    for (int j = 0; j < 4; j++) {
        int d = threadIdx.x + j * 256;
        float z = zr[d];
        float g = yr[d] * siluf(z);
        v[j] = g;
        ss += g * g;
    }
    float tot = blockReduceSum(ss);
    float scale = rsqrtf(tot * (1.0f / DINNER) + EPSF);
    #pragma unroll
    for (int j = 0; j < 4; j++) {
        int d = threadIdx.x + j * 256;
        float o = v[j] * scale * gw[d];
        __nv_bfloat16 hh, ll;
        bf16split(o, &hh, &ll);
        oh[(size_t)m * DINNER + d] = hh;
        ol[(size_t)m * DINNER + d] = ll;
    }
}

// ---------------- loss ----------------
__global__ void zero_loss_kernel(float* p) { *p = 0.f; }

__global__ void loss_kernel(const float* __restrict__ logits, const int* __restrict__ targets,
                            float* __restrict__ acc) {
    int gwid = (blockIdx.x * blockDim.x + threadIdx.x) >> 5;
    int lane = threadIdx.x & 31;
    if (gwid >= MTOK) return;
    const float* row = logits + (size_t)gwid * VOCAB;
    float mx = -1e30f;
    #pragma unroll
    for (int i = lane; i < VOCAB; i += 32) mx = fmaxf(mx, row[i]);
    #pragma unroll
    for (int o = 16; o > 0; o >>= 1) mx = fmaxf(mx, __shfl_xor_sync(0xffffffffu, mx, o));
    float s = 0.f;
    #pragma unroll
    for (int i = lane; i < VOCAB; i += 32) s += expf(row[i] - mx);
    #pragma unroll
    for (int o = 16; o > 0; o >>= 1) s += __shfl_xor_sync(0xffffffffu, s, o);
    if (lane == 0) {
        float lse = mx + logf(s);
        atomicAdd(acc, lse - row[targets[gwid]]);
    }
}

__global__ void fin_loss_kernel(const float* sum, float* dst) {
    *dst = (*sum) * (1.0f / (float)MTOK);
}

__global__ void copy_kernel(const float* __restrict__ src, float* __restrict__ dst, int n) {
    int i = blockIdx.x * blockDim.x + threadIdx.x;
    if (i < n) dst[i] = src[i];
}

// ---------------- host launcher ----------------
extern "C" void kernel_launch(void* const* d_in, const int* in_sizes, int n_in,
                              void* d_out, int out_size) {
    const int*   tokens   = (const int*)  d_in[0];
    const int*   targets  = (const int*)  d_in[1];
    const float* emb      = (const float*)d_in[2];
    const float* in_proj  = (const float*)d_in[3];
    const float* conv_w   = (const float*)d_in[4];
    const float* conv_b   = (const float*)d_in[5];
    const float* dt_bias  = (const float*)d_in[6];
    const float* A_log    = (const float*)d_in[7];
    const float* Dv       = (const float*)d_in[8];
    const float* gnorm    = (const float*)d_in[9];
    const float* out_proj = (const float*)d_in[10];
    const float* bnorm    = (const float*)d_in[11];
    const float* fnorm    = (const float*)d_in[12];
    float* out = (float*)d_out;

    float *hid, *res, *zx, *xbc, *dtp, *yb, *lgt, *lsum;
    __nv_bfloat16 *nh, *nl, *gh, *gl, *wih, *wil, *woh, *wol, *eh, *el;
    cudaGetSymbolAddress((void**)&hid,  g_hidden);
    cudaGetSymbolAddress((void**)&res,  g_resid);
    cudaGetSymbolAddress((void**)&zx,   g_zx);
    cudaGetSymbolAddress((void**)&xbc,  g_xbc);
    cudaGetSymbolAddress((void**)&dtp,  g_dt);
    cudaGetSymbolAddress((void**)&yb,   g_y);
    cudaGetSymbolAddress((void**)&lgt,  g_logits);
    cudaGetSymbolAddress((void**)&lsum, g_loss_sum);
    cudaGetSymbolAddress((void**)&nh,   g_nh);
    cudaGetSymbolAddress((void**)&nl,   g_nl);
    cudaGetSymbolAddress((void**)&gh,   g_gh);
    cudaGetSymbolAddress((void**)&gl,   g_gl);
    cudaGetSymbolAddress((void**)&wih,  g_wih);
    cudaGetSymbolAddress((void**)&wil,  g_wil);
    cudaGetSymbolAddress((void**)&woh,  g_woh);
    cudaGetSymbolAddress((void**)&wol,  g_wol);
    cudaGetSymbolAddress((void**)&eh,   g_eh);
    cudaGetSymbolAddress((void**)&el,   g_el);

    cudaFuncSetAttribute(gemm_bf16x3, cudaFuncAttributeMaxDynamicSharedMemorySize, GSMEM);

    {
        long t1 = (long)NLAYER * NINPAD * DMODEL;
        split_pad_kernel<<<(int)((t1 + 255) / 256), 256>>>(in_proj, wih, wil, DINPROJ, NINPAD, DMODEL, t1);
        long t2 = (long)NLAYER * DMODEL * DINNER;
        split_pad_kernel<<<(int)((t2 + 255) / 256), 256>>>(out_proj, woh, wol, DMODEL, DMODEL, DINNER, t2);
        long t3 = (long)VOCAB * DMODEL;
        split_pad_kernel<<<(int)((t3 + 255) / 256), 256>>>(emb, eh, el, VOCAB, VOCAB, DMODEL, t3);
    }

    embed_kernel<<<(MTOK * DMODEL + 255) / 256, 256>>>(tokens, emb, hid, res);

    for (int L = 0; L < NLAYER; ++L) {
        add_rms_kernel<<<MTOK, 128>>>(hid, res, bnorm + (size_t)L * DMODEL, nh, nl);

        dim3 g1(NINPAD / 128, MTOK / 128);
        gemm_bf16x3<<<g1, 256, GSMEM>>>(nh, nl,
                                        wih + (size_t)L * NINPAD * DMODEL,
                                        wil + (size_t)L * NINPAD * DMODEL,
                                        zx, MTOK, DINPROJ, DMODEL);

        dt_kernel<<<(MTOK * NHEADS + 255) / 256, 256>>>(zx, dt_bias + (size_t)L * NHEADS, dtp);

        conv_silu_kernel<<<(MTOK * CONVDIM + 255) / 256, 256>>>(
            zx, conv_w + (size_t)L * CONVDIM * DCONV, conv_b + (size_t)L * CONVDIM, xbc);

        ssd_scan_kernel<<<BATCH * NHEADS, 128>>>(xbc, dtp,
                                                 A_log + (size_t)L * NHEADS,
                                                 Dv + (size_t)L * NHEADS, yb);

        gate_rms_kernel<<<MTOK, 256>>>(zx, yb, gnorm + (size_t)L * DINNER, gh, gl);

        dim3 g2(DMODEL / 128, MTOK / 128);
        gemm_bf16x3<<<g2, 256, GSMEM>>>(gh, gl,
                                        woh + (size_t)L * DMODEL * DINNER,
                                        wol + (size_t)L * DMODEL * DINNER,
                                        hid, MTOK, DMODEL, DINNER);
    }

    add_rms_kernel<<<MTOK, 128>>>(hid, res, fnorm, nh, nl);

    dim3 g3(VOCAB / 128, MTOK / 128);
    gemm_bf16x3<<<g3, 256, GSMEM>>>(nh, nl, eh, el, lgt, MTOK, VOCAB, DMODEL);

    zero_loss_kernel<<<1, 1>>>(lsum);
    loss_kernel<<<(MTOK * 32 + 255) / 256, 256>>>(lgt, targets, lsum);

    const int LG = MTOK * VOCAB;
    if (out_size >= LG) {
        copy_kernel<<<(LG + 255) / 256, 256>>>(lgt, out, LG);
        if (out_size > LG) fin_loss_kernel<<<1, 1>>>(lsum, out + (out_size - 1));
    } else {
        fin_loss_kernel<<<1, 1>>>(lsum, out);
    }
}

// round 4
// speedup vs baseline: 1.8486x; 1.1834x over previous
#include <cuda_runtime.h>
#include <cuda_bf16.h>
#include <math.h>
#include <stdint.h>

// ---------------- problem constants ----------------
#define BATCH   16
#define SEQ     768
#define MTOK    (BATCH*SEQ)       // 12288
#define DMODEL  512
#define DSTATE  128
#define DCONV   4
#define DINNER  1024
#define HEADDIM 64
#define NHEADS  16
#define CONVDIM (DINNER + 2*DSTATE)            // 1280
#define DINPROJ (2*DINNER + 2*DSTATE + NHEADS) // 2320
#define NINPAD  2432                            // 19*128
#define NLAYER  28
#define VOCAB   256
#define EPSF    1e-5f

// ---------------- device scratch ----------------
__device__ float g_hidden[MTOK*DMODEL];
__device__ float g_resid [MTOK*DMODEL];
__device__ float g_zx    [(size_t)MTOK*DINPROJ];
__device__ float g_xbc   [(size_t)MTOK*CONVDIM];
__device__ float g_dt    [MTOK*NHEADS];
__device__ float g_y     [(size_t)MTOK*DINNER];
__device__ float g_logits[(size_t)MTOK*VOCAB];
__device__ float g_loss_sum;

__device__ __nv_bfloat16 g_nh[MTOK*DMODEL],  g_nl[MTOK*DMODEL];
__device__ __nv_bfloat16 g_gh[MTOK*DINNER],  g_gl[MTOK*DINNER];
__device__ __nv_bfloat16 g_wih[(size_t)NLAYER*NINPAD*DMODEL], g_wil[(size_t)NLAYER*NINPAD*DMODEL];
__device__ __nv_bfloat16 g_woh[(size_t)NLAYER*DMODEL*DINNER], g_wol[(size_t)NLAYER*DMODEL*DINNER];
__device__ __nv_bfloat16 g_eh[VOCAB*DMODEL], g_el[VOCAB*DMODEL];

// ---------------- PTX helpers (family-safe) ----------------
__device__ __forceinline__ uint32_t smem_u32(const void* p) {
    uint32_t a;
    asm("{ .reg .u64 t; cvta.to.shared.u64 t, %1; cvt.u32.u64 %0, t; }" : "=r"(a) : "l"(p));
    return a;
}
__device__ __forceinline__ void cp16(uint32_t dst, const void* src) {
    asm volatile("cp.async.cg.shared.global [%0], [%1], 16;" :: "r"(dst), "l"(src));
}
__device__ __forceinline__ void ldm_x4(uint32_t addr, uint32_t& r0, uint32_t& r1, uint32_t& r2, uint32_t& r3) {
    asm volatile("ldmatrix.sync.aligned.m8n8.x4.shared.b16 {%0,%1,%2,%3}, [%4];"
                 : "=r"(r0), "=r"(r1), "=r"(r2), "=r"(r3) : "r"(addr));
}
__device__ __forceinline__ void mma_bf16(float* c, const uint32_t* a, const uint32_t* b) {
    asm volatile(
        "mma.sync.aligned.m16n8k16.row.col.f32.bf16.bf16.f32 "
        "{%0,%1,%2,%3}, {%4,%5,%6,%7}, {%8,%9}, {%0,%1,%2,%3};"
        : "+f"(c[0]), "+f"(c[1]), "+f"(c[2]), "+f"(c[3])
        : "r"(a[0]), "r"(a[1]), "r"(a[2]), "r"(a[3]), "r"(b[0]), "r"(b[1]));
}
// packed f32x2 (sm_100 family)
typedef unsigned long long u64t;
__device__ __forceinline__ u64t pack2(float x, float y) {
    u64t r; asm("mov.b64 %0, {%1, %2};" : "=l"(r) : "f"(x), "f"(y)); return r;
}
__device__ __forceinline__ u64t mul2(u64t a, u64t b) {
    u64t d; asm("mul.rn.f32x2 %0, %1, %2;" : "=l"(d) : "l"(a), "l"(b)); return d;
}
__device__ __forceinline__ u64t fma2(u64t a, u64t b, u64t c) {
    u64t d; asm("fma.rn.f32x2 %0, %1, %2, %3;" : "=l"(d) : "l"(a), "l"(b), "l"(c)); return d;
}
__device__ __forceinline__ void unpack2(u64t v, float& x, float& y) {
    asm("mov.b64 {%0, %1}, %2;" : "=f"(x), "=f"(y) : "l"(v));
}

// ---------------- bf16x3 GEMM via mma.sync ----------------
// C[M,N] = A[M,K]*B[N,K]^T, fp32 C. A,B as bf16 hi/lo pairs.
// 128x128 tile, KC=32, 2-stage cp.async pipeline, 256 threads (8 warps 2x4),
// 2 CTAs/SM. smem row: 64B data + 16B pad = 80B stride.
#define ROWB   80
#define SUBT   (128*ROWB)      // 10240 per subtile
#define STAGEB (4*SUBT)        // 40960: Ah, Al, Bh, Bl
#define GSMEM  (2*STAGEB)      // 81920

__device__ __forceinline__ void fill_stage(uint32_t st,
        const __nv_bfloat16* __restrict__ Ah, const __nv_bfloat16* __restrict__ Al,
        const __nv_bfloat16* __restrict__ Bh, const __nv_bfloat16* __restrict__ Bl,
        int bm, int bn, int K, int kc, int tid)
{
    const size_t k0 = (size_t)kc * 32;
    const __nv_bfloat16* srcs[4] = {Ah + (size_t)bm * K + k0, Al + (size_t)bm * K + k0,
                                    Bh + (size_t)bn * K + k0, Bl + (size_t)bn * K + k0};
    #pragma unroll
    for (int s = 0; s < 4; ++s) {
        const __nv_bfloat16* base = srcs[s];
        uint32_t sd = st + s * SUBT;
        #pragma unroll
        for (int i = 0; i < 2; ++i) {
            int lin = tid + (i << 8);
            int row = lin >> 2;
            int ch  = lin & 3;
            cp16(sd + row * ROWB + ch * 16, base + (size_t)row * K + ch * 8);
        }
    }
    asm volatile("cp.async.commit_group;" ::: "memory");
}

__global__ void __launch_bounds__(256, 2) gemm_bf16x3(
    const __nv_bfloat16* __restrict__ Ah, const __nv_bfloat16* __restrict__ Al,
    const __nv_bfloat16* __restrict__ Bh, const __nv_bfloat16* __restrict__ Bl,
    float* __restrict__ C, int M, int N, int K)
{
    extern __shared__ char smem[];
    const uint32_t sb = smem_u32(smem);
    const int tid  = threadIdx.x;
    const int wid  = tid >> 5, lane = tid & 31;
    const int wm   = wid >> 2, wn = wid & 3;
    const int bm   = blockIdx.y * 128, bn = blockIdx.x * 128;

    float acc[4][4][4];
    #pragma unroll
    for (int i = 0; i < 4; i++)
        #pragma unroll
        for (int j = 0; j < 4; j++)
            #pragma unroll
            for (int q = 0; q < 4; q++) acc[i][j][q] = 0.f;

    const int nc = K >> 5;

    fill_stage(sb + 0 * STAGEB, Ah, Al, Bh, Bl, bm, bn, K, 0, tid);
    if (nc > 1) fill_stage(sb + 1 * STAGEB, Ah, Al, Bh, Bl, bm, bn, K, 1, tid);

    const int a_r  = lane & 15;
    const int a_k  = lane >> 4;
    const int b_r  = ((lane >> 4) << 3) + (lane & 7);
    const int b_k  = (lane >> 3) & 1;

    for (int c = 0; c < nc; ++c) {
        const uint32_t st = sb + (uint32_t)(c & 1) * STAGEB;
        if (c + 1 < nc) asm volatile("cp.async.wait_group 1;" ::: "memory");
        else            asm volatile("cp.async.wait_group 0;" ::: "memory");
        __syncthreads();

        const uint32_t a_base = st + (uint32_t)(wm * 64 + a_r) * ROWB + a_k * 16;
        const uint32_t b_base = st + 2 * SUBT + (uint32_t)(wn * 32 + b_r) * ROWB + b_k * 16;

        #pragma unroll
        for (int ks = 0; ks < 2; ++ks) {
            uint32_t bh[4][2], bl[4][2];
            #pragma unroll
            for (int bi = 0; bi < 2; ++bi) {
                uint32_t addr = b_base + (uint32_t)(bi * 16) * ROWB + ks * 32;
                ldm_x4(addr,        bh[2*bi][0], bh[2*bi][1], bh[2*bi+1][0], bh[2*bi+1][1]);
                ldm_x4(addr + SUBT, bl[2*bi][0], bl[2*bi][1], bl[2*bi+1][0], bl[2*bi+1][1]);
            }
            #pragma unroll
            for (int mi = 0; mi < 4; ++mi) {
                uint32_t ah[4], al[4];
                uint32_t addr = a_base + (uint32_t)(mi * 16) * ROWB + ks * 32;
                ldm_x4(addr,        ah[0], ah[1], ah[2], ah[3]);
                ldm_x4(addr + SUBT, al[0], al[1], al[2], al[3]);
                #pragma unroll
                for (int ni = 0; ni < 4; ++ni) {
                    mma_bf16(acc[mi][ni], ah, bh[ni]);
                    mma_bf16(acc[mi][ni], ah, bl[ni]);
                    mma_bf16(acc[mi][ni], al, bh[ni]);
                }
            }
        }
        __syncthreads();
        int cn = c + 2;
        if (cn < nc)
            fill_stage(st, Ah, Al, Bh, Bl, bm, bn, K, cn, tid);
    }

    const int r  = lane >> 2;
    const int cc = (lane & 3) << 1;
    #pragma unroll
    for (int mi = 0; mi < 4; ++mi) {
        int m0 = bm + wm * 64 + mi * 16 + r;
        #pragma unroll
        for (int ni = 0; ni < 4; ++ni) {
            int n0 = bn + wn * 32 + ni * 8 + cc;
            if (n0 < N) {
                *reinterpret_cast<float2*>(C + (size_t)m0 * N + n0) =
                    make_float2(acc[mi][ni][0], acc[mi][ni][1]);
                *reinterpret_cast<float2*>(C + (size_t)(m0 + 8) * N + n0) =
                    make_float2(acc[mi][ni][2], acc[mi][ni][3]);
            }
        }
    }
}

// ---------------- generic helpers ----------------
__device__ __forceinline__ float blockReduceSum(float v) {
    __shared__ float sh[32];
    int lane = threadIdx.x & 31, wid = threadIdx.x >> 5;
    #pragma unroll
    for (int o = 16; o > 0; o >>= 1) v += __shfl_xor_sync(0xffffffffu, v, o);
    if (lane == 0) sh[wid] = v;
    __syncthreads();
    if (threadIdx.x == 0) {
        float t = 0.f;
        int nw = (blockDim.x + 31) >> 5;
        for (int i = 0; i < nw; i++) t += sh[i];
        sh[0] = t;
    }
    __syncthreads();
    return sh[0];
}
__device__ __forceinline__ float siluf(float x) { return x / (1.0f + expf(-x)); }

__device__ __forceinline__ void bf16split(float v, __nv_bfloat16* h, __nv_bfloat16* l) {
    __nv_bfloat16 hb = __float2bfloat16(v);
    *h = hb;
    *l = __float2bfloat16(v - __bfloat162float(hb));
}

// ---------------- weight split (with row padding) ----------------
__global__ void split_pad_kernel(const float* __restrict__ src, __nv_bfloat16* __restrict__ h,
                                 __nv_bfloat16* __restrict__ l, int nt, int np, int K, long total) {
    long idx = (long)blockIdx.x * blockDim.x + threadIdx.x;
    if (idx >= total) return;
    int k = (int)(idx % K);
    long t = idx / K;
    int r  = (int)(t % np);
    int ly = (int)(t / np);
    float v = (r < nt) ? src[((size_t)ly * nt + r) * K + k] : 0.0f;
    __nv_bfloat16 hh, ll;
    bf16split(v, &hh, &ll);
    h[idx] = hh; l[idx] = ll;
}

// ---------------- embedding + residual init ----------------
__global__ void embed_kernel(const int* __restrict__ tokens, const float* __restrict__ emb,
                             float* __restrict__ hid, float* __restrict__ res) {
    int idx = blockIdx.x * blockDim.x + threadIdx.x;
    if (idx >= MTOK * DMODEL) return;
    int m = idx >> 9;
    int d = idx & 511;
    hid[idx] = emb[tokens[m] * DMODEL + d];
    res[idx] = 0.0f;
}

// res += h ; out = rms(res)*w -> bf16 hi/lo
__global__ void add_rms_kernel(const float* __restrict__ h, float* __restrict__ res,
                               const float* __restrict__ w,
                               __nv_bfloat16* __restrict__ oh, __nv_bfloat16* __restrict__ ol) {
    int m = blockIdx.x;
    const float* hr = h + (size_t)m * DMODEL;
    float* rr = res + (size_t)m * DMODEL;
    float v[4]; float ss = 0.f;
    #pragma unroll
    for (int j = 0; j < 4; j++) {
        int d = threadIdx.x + j * 128;
        float x = hr[d] + rr[d];
        rr[d] = x;
        v[j] = x;
        ss += x * x;
    }
    float tot = blockReduceSum(ss);
    float scale = rsqrtf(tot * (1.0f / DMODEL) + EPSF);
    #pragma unroll
    for (int j = 0; j < 4; j++) {
        int d = threadIdx.x + j * 128;
        float o = v[j] * scale * w[d];
        __nv_bfloat16 hh, ll;
        bf16split(o, &hh, &ll);
        oh[(size_t)m * DMODEL + d] = hh;
        ol[(size_t)m * DMODEL + d] = ll;
    }
}

// ---------------- dt = softplus ----------------
__global__ void dt_kernel(const float* __restrict__ zx, const float* __restrict__ dt_bias,
                          float* __restrict__ dt) {
    int idx = blockIdx.x * blockDim.x + threadIdx.x;
    if (idx >= MTOK * NHEADS) return;
    int m = idx >> 4;
    int h = idx & 15;
    float x = zx[(size_t)m * DINPROJ + (2 * DINNER + 2 * DSTATE) + h] + dt_bias[h];
    dt[idx] = (x > 20.0f) ? x : log1pf(expf(x));
}

// ---------------- causal depthwise conv + silu ----------------
__global__ void conv_silu_kernel(const float* __restrict__ zx, const float* __restrict__ w,
                                 const float* __restrict__ bias, float* __restrict__ out) {
    int idx = blockIdx.x * blockDim.x + threadIdx.x;
    if (idx >= MTOK * CONVDIM) return;
    int c = idx % CONVDIM;
    int m = idx / CONVDIM;
    int l = m % SEQ;
    int b = m / SEQ;
    float acc = bias[c];
    #pragma unroll
    for (int k = 0; k < DCONV; k++) {
        int lp = l + k - (DCONV - 1);
        if (lp >= 0)
            acc = fmaf(zx[((size_t)(b * SEQ + lp)) * DINPROJ + DINNER + c], w[c * DCONV + k], acc);
    }
    out[(size_t)m * CONVDIM + c] = siluf(acc);
}

// ---------------- SSD sequential scan ----------------
// 128 blocks (b, head-pair), 256 threads: two heads of same batch share B/C.
// State packed as f32x2, cp.async prefetch distance 2 (3 buffers).
__global__ void __launch_bounds__(256) ssd_scan_kernel(
        const float* __restrict__ xbc, const float* __restrict__ dt,
        const float* __restrict__ A_log, const float* __restrict__ Dv,
        float* __restrict__ y)
{
    const int blk  = blockIdx.x;          // 0..127
    const int b    = blk >> 3, pair = blk & 7;
    const int tid  = threadIdx.x;
    const int hsel = tid >> 7;            // which head of the pair
    const int wg   = tid & 127;
    const int p    = wg >> 1;
    const int nh   = wg & 1;
    const int hh   = pair * 2 + hsel;
    const float A  = -expf(A_log[hh]);
    const float Dh = Dv[hh];

    __shared__ __align__(16) float sBC[3][256];
    __shared__ __align__(16) float sX [3][128];
    __shared__ __align__(16) float sDT[3][16];

    u64t hs2[32];
    #pragma unroll
    for (int i = 0; i < 32; i++) hs2[i] = 0ULL;

    const size_t base = (size_t)b * SEQ;
    const uint32_t bcAddr = smem_u32(&sBC[0][0]);
    const uint32_t xAddr  = smem_u32(&sX[0][0]);
    const uint32_t dtAddr = smem_u32(&sDT[0][0]);

    // prefetch helper (all threads execute commit; groups are per-thread)
    #define SSD_PREFETCH(l) do {                                             \
        int _buf = (l) % 3;                                                   \
        const float* _row = xbc + (base + (l)) * CONVDIM;                     \
        if (tid < 64)       cp16(bcAddr + _buf * 1024 + tid * 16, _row + DINNER + tid * 4); \
        else if (tid < 96)  cp16(xAddr + _buf * 512 + (tid - 64) * 16, _row + pair * 128 + (tid - 64) * 4); \
        else if (tid < 100) cp16(dtAddr + _buf * 64 + (tid - 96) * 16, dt + (base + (l)) * NHEADS + (tid - 96) * 4); \
        asm volatile("cp.async.commit_group;" ::: "memory");                  \
    } while (0)

    SSD_PREFETCH(0);
    SSD_PREFETCH(1);

    for (int l = 0; l < SEQ; ++l) {
        if (l + 1 < SEQ) asm volatile("cp.async.wait_group 1;" ::: "memory");
        else             asm volatile("cp.async.wait_group 0;" ::: "memory");
        __syncthreads();
        const int buf = l % 3;
        if (l + 2 < SEQ) SSD_PREFETCH(l + 2);

        const float dtv = sDT[buf][hh];
        const float xp  = sX[buf][hsel * 64 + p];
        const float dA  = expf(dtv * A);
        const float dbx = dtv * xp;
        const u64t dA2  = pack2(dA, dA);
        const u64t dbx2 = pack2(dbx, dbx);

        const u64t* B2 = reinterpret_cast<const u64t*>(&sBC[buf][nh * 64]);
        const u64t* C2 = reinterpret_cast<const u64t*>(&sBC[buf][128 + nh * 64]);
        u64t accA = 0ULL, accB = 0ULL;
        #pragma unroll
        for (int i = 0; i < 16; ++i) {
            u64t b0 = B2[2*i], b1 = B2[2*i+1];
            u64t c0 = C2[2*i], c1 = C2[2*i+1];
            hs2[2*i]   = fma2(dA2, hs2[2*i],   mul2(dbx2, b0));
            accA       = fma2(hs2[2*i],   c0, accA);
            hs2[2*i+1] = fma2(dA2, hs2[2*i+1], mul2(dbx2, b1));
            accB       = fma2(hs2[2*i+1], c1, accB);
        }
        float ax, ay, bx, by;
        unpack2(accA, ax, ay);
        unpack2(accB, bx, by);
        float sum = (ax + ay) + (bx + by);
        sum += __shfl_xor_sync(0xffffffffu, sum, 1);
        if (nh == 0)
            y[(base + l) * DINNER + hh * HEADDIM + p] = fmaf(Dh, xp, sum);
    }
    #undef SSD_PREFETCH
}

// ---------------- gated RMSNorm -> bf16 hi/lo ----------------
__global__ void gate_rms_kernel(const float* __restrict__ zx, const float* __restrict__ y,
                                const float* __restrict__ gw,
                                __nv_bfloat16* __restrict__ oh, __nv_bfloat16* __restrict__ ol) {
    int m = blockIdx.x;
    const float* zr = zx + (size_t)m * DINPROJ;
    const float* yr = y + (size_t)m * DINNER;
    float v[4]; float ss = 0.f;
    #pragma unroll
    for (int j = 0; j < 4; j++) {
        int d = threadIdx.x + j * 256;
        float z = zr[d];
        float g = yr[d] * siluf(z);
        v[j] = g;
        ss += g * g;
    }
    float tot = blockReduceSum(ss);
    float scale = rsqrtf(tot * (1.0f / DINNER) + EPSF);
    #pragma unroll
    for (int j = 0; j < 4; j++) {
        int d = threadIdx.x + j * 256;
        float o = v[j] * scale * gw[d];
        __nv_bfloat16 hh, ll;
        bf16split(o, &hh, &ll);
        oh[(size_t)m * DINNER + d] = hh;
        ol[(size_t)m * DINNER + d] = ll;
    }
}

// ---------------- loss ----------------
__global__ void zero_loss_kernel(float* p) { *p = 0.f; }

__global__ void loss_kernel(const float* __restrict__ logits, const int* __restrict__ targets,
                            float* __restrict__ acc) {
    int gwid = (blockIdx.x * blockDim.x + threadIdx.x) >> 5;
    int lane = threadIdx.x & 31;
    if (gwid >= MTOK) return;
    const float* row = logits + (size_t)gwid * VOCAB;
    float mx = -1e30f;
    #pragma unroll
    for (int i = lane; i < VOCAB; i += 32) mx = fmaxf(mx, row[i]);
    #pragma unroll
    for (int o = 16; o > 0; o >>= 1) mx = fmaxf(mx, __shfl_xor_sync(0xffffffffu, mx, o));
    float s = 0.f;
    #pragma unroll
    for (int i = lane; i < VOCAB; i += 32) s += expf(row[i] - mx);
    #pragma unroll
    for (int o = 16; o > 0; o >>= 1) s += __shfl_xor_sync(0xffffffffu, s, o);
    if (lane == 0) {
        float lse = mx + logf(s);
        atomicAdd(acc, lse - row[targets[gwid]]);
    }
}

__global__ void fin_loss_kernel(const float* sum, float* dst) {
    *dst = (*sum) * (1.0f / (float)MTOK);
}

// ---------------- host launcher ----------------
extern "C" void kernel_launch(void* const* d_in, const int* in_sizes, int n_in,
                              void* d_out, int out_size) {
    const int*   tokens   = (const int*)  d_in[0];
    const int*   targets  = (const int*)  d_in[1];
    const float* emb      = (const float*)d_in[2];
    const float* in_proj  = (const float*)d_in[3];
    const float* conv_w   = (const float*)d_in[4];
    const float* conv_b   = (const float*)d_in[5];
    const float* dt_bias  = (const float*)d_in[6];
    const float* A_log    = (const float*)d_in[7];
    const float* Dv       = (const float*)d_in[8];
    const float* gnorm    = (const float*)d_in[9];
    const float* out_proj = (const float*)d_in[10];
    const float* bnorm    = (const float*)d_in[11];
    const float* fnorm    = (const float*)d_in[12];
    float* out = (float*)d_out;

    float *hid, *res, *zx, *xbc, *dtp, *yb, *lgt, *lsum;
    __nv_bfloat16 *nh, *nl, *gh, *gl, *wih, *wil, *woh, *wol, *eh, *el;
    cudaGetSymbolAddress((void**)&hid,  g_hidden);
    cudaGetSymbolAddress((void**)&res,  g_resid);
    cudaGetSymbolAddress((void**)&zx,   g_zx);
    cudaGetSymbolAddress((void**)&xbc,  g_xbc);
    cudaGetSymbolAddress((void**)&dtp,  g_dt);
    cudaGetSymbolAddress((void**)&yb,   g_y);
    cudaGetSymbolAddress((void**)&lgt,  g_logits);
    cudaGetSymbolAddress((void**)&lsum, g_loss_sum);
    cudaGetSymbolAddress((void**)&nh,   g_nh);
    cudaGetSymbolAddress((void**)&nl,   g_nl);
    cudaGetSymbolAddress((void**)&gh,   g_gh);
    cudaGetSymbolAddress((void**)&gl,   g_gl);
    cudaGetSymbolAddress((void**)&wih,  g_wih);
    cudaGetSymbolAddress((void**)&wil,  g_wil);
    cudaGetSymbolAddress((void**)&woh,  g_woh);
    cudaGetSymbolAddress((void**)&wol,  g_wol);
    cudaGetSymbolAddress((void**)&eh,   g_eh);
    cudaGetSymbolAddress((void**)&el,   g_el);

    cudaFuncSetAttribute(gemm_bf16x3, cudaFuncAttributeMaxDynamicSharedMemorySize, GSMEM);

    {
        long t1 = (long)NLAYER * NINPAD * DMODEL;
        split_pad_kernel<<<(int)((t1 + 255) / 256), 256>>>(in_proj, wih, wil, DINPROJ, NINPAD, DMODEL, t1);
        long t2 = (long)NLAYER * DMODEL * DINNER;
        split_pad_kernel<<<(int)((t2 + 255) / 256), 256>>>(out_proj, woh, wol, DMODEL, DMODEL, DINNER, t2);
        long t3 = (long)VOCAB * DMODEL;
        split_pad_kernel<<<(int)((t3 + 255) / 256), 256>>>(emb, eh, el, VOCAB, VOCAB, DMODEL, t3);
    }

    embed_kernel<<<(MTOK * DMODEL + 255) / 256, 256>>>(tokens, emb, hid, res);

    for (int L = 0; L < NLAYER; ++L) {
        add_rms_kernel<<<MTOK, 128>>>(hid, res, bnorm + (size_t)L * DMODEL, nh, nl);

        dim3 g1(NINPAD / 128, MTOK / 128);
        gemm_bf16x3<<<g1, 256, GSMEM>>>(nh, nl,
                                        wih + (size_t)L * NINPAD * DMODEL,
                                        wil + (size_t)L * NINPAD * DMODEL,
                                        zx, MTOK, DINPROJ, DMODEL);

        dt_kernel<<<(MTOK * NHEADS + 255) / 256, 256>>>(zx, dt_bias + (size_t)L * NHEADS, dtp);

        conv_silu_kernel<<<(MTOK * CONVDIM + 255) / 256, 256>>>(
            zx, conv_w + (size_t)L * CONVDIM * DCONV, conv_b + (size_t)L * CONVDIM, xbc);

        ssd_scan_kernel<<<BATCH * NHEADS / 2, 256>>>(xbc, dtp,
                                                     A_log + (size_t)L * NHEADS,
                                                     Dv + (size_t)L * NHEADS, yb);

        gate_rms_kernel<<<MTOK, 256>>>(zx, yb, gnorm + (size_t)L * DINNER, gh, gl);

        dim3 g2(DMODEL / 128, MTOK / 128);
        gemm_bf16x3<<<g2, 256, GSMEM>>>(gh, gl,
                                        woh + (size_t)L * DMODEL * DINNER,
                                        wol + (size_t)L * DMODEL * DINNER,
                                        hid, MTOK, DMODEL, DINNER);
    }

    add_rms_kernel<<<MTOK, 128>>>(hid, res, fnorm, nh, nl);

    const int LG = MTOK * VOCAB;
    float* logits_dst = (out_size >= LG) ? out : lgt;
    dim3 g3(VOCAB / 128, MTOK / 128);
    gemm_bf16x3<<<g3, 256, GSMEM>>>(nh, nl, eh, el, logits_dst, MTOK, VOCAB, DMODEL);

    zero_loss_kernel<<<1, 1>>>(lsum);
    loss_kernel<<<(MTOK * 32 + 255) / 256, 256>>>(logits_dst, targets, lsum);

    if (out_size > LG)       fin_loss_kernel<<<1, 1>>>(lsum, out + (out_size - 1));
    else if (out_size < LG)  fin_loss_kernel<<<1, 1>>>(lsum, out);
}